// round 15
// baseline (speedup 1.0000x reference)
#include <cuda_runtime.h>
#include <cuda_bf16.h>
#include <math.h>
#include <stdint.h>

#define Bsz 4
#define Lq  1024
#define Dm  1024
#define NH  16
#define HD  64
#define L2E 1.4426950408889634f

// ---------------- scratch (static device globals; no allocation) ----------------
__device__ int   g_mask_is_word;
__device__ int   g_am_nonzero;

__device__ __align__(256) __nv_bfloat16 g_xhi3[3][Bsz * Lq * Dm];
__device__ __align__(256) __nv_bfloat16 g_xlo3[3][Bsz * Lq * Dm];
__device__ __align__(256) __nv_bfloat16 g_whi[4][3 * Dm * Dm];  // [sel][t][o][i]
__device__ __align__(256) __nv_bfloat16 g_wlo[4][3 * Dm * Dm];
__device__ __align__(256) __nv_bfloat16 g_qhi[Bsz * Lq * Dm];
__device__ __align__(256) __nv_bfloat16 g_qlo[Bsz * Lq * Dm];
__device__ __align__(256) __nv_bfloat16 g_khi[Bsz * Lq * Dm];
__device__ __align__(256) __nv_bfloat16 g_klo[Bsz * Lq * Dm];
__device__ __align__(256) __nv_bfloat16 g_vhi[Bsz * Lq * Dm];
__device__ __align__(256) __nv_bfloat16 g_vlo[Bsz * Lq * Dm];

// ================= warp-MMA helpers =================
__device__ __forceinline__ uint32_t smem_u32(const void* p) {
    uint32_t a;
    asm("{ .reg .u64 t; cvta.to.shared.u64 t, %1; cvt.u32.u64 %0, t; }"
        : "=r"(a) : "l"(p));
    return a;
}
__device__ __forceinline__ void ldsm_x4(uint32_t* r, uint32_t addr) {
    asm volatile("ldmatrix.sync.aligned.m8n8.x4.shared.b16 {%0,%1,%2,%3}, [%4];"
                 : "=r"(r[0]), "=r"(r[1]), "=r"(r[2]), "=r"(r[3]) : "r"(addr));
}
__device__ __forceinline__ void ldsm_x4_t(uint32_t* r, uint32_t addr) {
    asm volatile("ldmatrix.sync.aligned.m8n8.x4.trans.shared.b16 {%0,%1,%2,%3}, [%4];"
                 : "=r"(r[0]), "=r"(r[1]), "=r"(r[2]), "=r"(r[3]) : "r"(addr));
}
__device__ __forceinline__ void mma16816(float* c, const uint32_t* a,
                                          const uint32_t b0, const uint32_t b1) {
    asm volatile(
        "mma.sync.aligned.m16n8k16.row.col.f32.bf16.bf16.f32 "
        "{%0,%1,%2,%3}, {%4,%5,%6,%7}, {%8,%9}, {%0,%1,%2,%3};"
        : "+f"(c[0]), "+f"(c[1]), "+f"(c[2]), "+f"(c[3])
        : "r"(a[0]), "r"(a[1]), "r"(a[2]), "r"(a[3]), "r"(b0), "r"(b1));
}
__device__ __forceinline__ void cp_async16(uint32_t dst, const void* src, int src_bytes) {
    asm volatile("cp.async.cg.shared.global [%0], [%1], 16, %2;"
                 :: "r"(dst), "l"(src), "r"(src_bytes) : "memory");
}
#define CP_COMMIT() asm volatile("cp.async.commit_group;" ::: "memory")
#define CP_WAIT1()  asm volatile("cp.async.wait_group 1;" ::: "memory")
#define CP_WAIT0()  asm volatile("cp.async.wait_group 0;" ::: "memory")

__device__ __forceinline__ void split_bf16(float x, __nv_bfloat16& h, __nv_bfloat16& l) {
    h = __float2bfloat16_rn(x);
    l = __float2bfloat16_rn(x - __bfloat162float(h));
}
__device__ __forceinline__ uint32_t pack2(__nv_bfloat16 a, __nv_bfloat16 b) {
    __nv_bfloat162 t(a, b);
    return *reinterpret_cast<uint32_t*>(&t);
}

// ---------------- mask / attn_mask dtype+content detection ----------------
__global__ void detect_mask(const unsigned char* __restrict__ m) {
    __shared__ int red[256];
    int tid = threadIdx.x;
    if (tid == 0 && blockIdx.x == 0) g_am_nonzero = 0;
    int c = 0;
    for (int i = tid; i < 4096; i += 256) c += (m[i] != 0);
    red[tid] = c;
    __syncthreads();
    for (int s = 128; s > 0; s >>= 1) {
        if (tid < s) red[tid] += red[tid + s];
        __syncthreads();
    }
    if (tid == 0) g_mask_is_word = (red[0] < 1536) ? 1 : 0;
}

__global__ void detect_am(const float* __restrict__ am) {
    int i = (blockIdx.x * 256 + threadIdx.x) * 4;
    float4 v = *reinterpret_cast<const float4*>(am + i);
    if (v.x != 0.f || v.y != 0.f || v.z != 0.f || v.w != 0.f)
        atomicOr(&g_am_nonzero, 1);
}

// ---------------- preps ----------------
__global__ void prep_x3(const float* __restrict__ x0, const float* __restrict__ x1,
                        const float* __restrict__ x2) {
    int z = blockIdx.y;
    const float* src = (z == 0) ? x0 : (z == 1) ? x1 : x2;
    int idx = blockIdx.x * blockDim.x + threadIdx.x;
    float4 v = reinterpret_cast<const float4*>(src)[idx];
    __nv_bfloat16 h0, l0, h1, l1, h2, l2, h3, l3;
    split_bf16(v.x, h0, l0); split_bf16(v.y, h1, l1);
    split_bf16(v.z, h2, l2); split_bf16(v.w, h3, l3);
    reinterpret_cast<__nv_bfloat162*>(g_xhi3[z])[idx * 2 + 0] = __nv_bfloat162(h0, h1);
    reinterpret_cast<__nv_bfloat162*>(g_xhi3[z])[idx * 2 + 1] = __nv_bfloat162(h2, h3);
    reinterpret_cast<__nv_bfloat162*>(g_xlo3[z])[idx * 2 + 0] = __nv_bfloat162(l0, l1);
    reinterpret_cast<__nv_bfloat162*>(g_xlo3[z])[idx * 2 + 1] = __nv_bfloat162(l2, l3);
}

// w[o][i][t] -> whi/wlo[sel][t][o][i]; grid (12288, 4)
__global__ void prep_w4(const float* __restrict__ w0, const float* __restrict__ w1,
                        const float* __restrict__ w2, const float* __restrict__ w3) {
    int sel = blockIdx.y;
    const float* w = (sel == 0) ? w0 : (sel == 1) ? w1 : (sel == 2) ? w2 : w3;
    int j = blockIdx.x * blockDim.x + threadIdx.x;
    int t = j >> 20;
    int rem = j & 0xFFFFF;
    int o = rem >> 10;
    int i = rem & 1023;
    float v = w[((size_t)o * Dm + i) * 3 + t];
    __nv_bfloat16 h, l;
    split_bf16(v, h, l);
    g_whi[sel][j] = h;
    g_wlo[sel][j] = l;
}

// ---------------- conv core (256 threads / 8 warps, warp tile 32x32) ------------
#define A_BYTES (130 * 64)
#define B_BYTES (64 * 64)
#define CONV_SMEM (4 * A_BYTES + 4 * B_BYTES)   // 49664 bytes

__device__ __forceinline__ uint32_t csw(int row, int colb) {
    return (uint32_t)(row * 64 + (colb ^ (((row >> 1) & 3) << 4)));
}

__device__ __forceinline__ void conv_core(
    const __nv_bfloat16* __restrict__ xhi, const __nv_bfloat16* __restrict__ xlo,
    const __nv_bfloat16* __restrict__ whi, const __nv_bfloat16* __restrict__ wlo,
    char* sm, int b, int lbase, int colTile, float acc[2][4][4])
{
    int tid = threadIdx.x;
    int lane = tid & 31;
    int w = tid >> 5;            // 0..7
    int wm = (w >> 1) * 32;      // 0,32,64,96
    int wn = (w & 1) * 32;       // 0,32
    int lrow = lane & 15;
    int lhalf = (lane >> 4) * 8;

    uint32_t base = smem_u32(sm);
    uint32_t aB[2][2], bB[2][2];
#pragma unroll
    for (int s = 0; s < 2; s++)
#pragma unroll
        for (int hl = 0; hl < 2; hl++) {
            aB[s][hl] = base + (uint32_t)((s * 2 + hl) * A_BYTES);
            bB[s][hl] = base + (uint32_t)(4 * A_BYTES + (s * 2 + hl) * B_BYTES);
        }

    auto stageA = [&](int k0, int s) {
        for (int v = tid; v < 130 * 4; v += 256) {
            int row = v >> 2;
            int colb = (v & 3) << 4;
            int l = lbase + row - 1;
            int nb = (l >= 0 && l < Lq) ? 16 : 0;
            int lc = l < 0 ? 0 : (l > Lq - 1 ? Lq - 1 : l);
            size_t g = ((size_t)(b << 10) + lc) * Dm + k0 + (colb >> 1);
            uint32_t doff = csw(row, colb);
            cp_async16(aB[s][0] + doff, xhi + g, nb);
            cp_async16(aB[s][1] + doff, xlo + g, nb);
        }
    };
    auto stageB = [&](int k0, int t, int s) {
        const __nv_bfloat16* wh = whi + ((size_t)t << 20);
        const __nv_bfloat16* wl = wlo + ((size_t)t << 20);
        for (int v = tid; v < 256; v += 256) {
            int row = v >> 2;
            int colb = (v & 3) << 4;
            size_t gw = (size_t)(colTile + row) * Dm + k0 + (colb >> 1);
            uint32_t doff = csw(row, colb);
            cp_async16(bB[s][0] + doff, wh + gw, 16);
            cp_async16(bB[s][1] + doff, wl + gw, 16);
        }
    };

    stageA(0, 0);
    stageB(0, 0, 0);
    CP_COMMIT();

    for (int it = 0; it < 96; ++it) {
        int t = it - (it / 3) * 3;
        int aCur = (it / 3) & 1;
        int bCur = it & 1;

        int itn = it + 1;
        if (itn < 96) {
            int kn = itn / 3;
            int tn = itn - kn * 3;
            if (tn == 0) stageA(kn * 32, kn & 1);
            stageB(kn * 32, tn, itn & 1);
        }
        CP_COMMIT();
        CP_WAIT1();
        __syncthreads();

#pragma unroll
        for (int ks = 0; ks < 32; ks += 16) {
            int colb = (ks + lhalf) * 2;
            uint32_t a_hi[2][4], a_lo[2][4];
#pragma unroll
            for (int mt = 0; mt < 2; mt++) {
                uint32_t off = csw(wm + mt * 16 + lrow + t, colb);
                ldsm_x4(a_hi[mt], aB[aCur][0] + off);
                ldsm_x4(a_lo[mt], aB[aCur][1] + off);
            }
            uint32_t b_hi[4][2], b_lo[4][2];
#pragma unroll
            for (int p = 0; p < 2; p++) {
                uint32_t off = csw(wn + p * 16 + lrow, colb);
                uint32_t q[4];
                ldsm_x4(q, bB[bCur][0] + off);
                b_hi[2 * p][0] = q[0]; b_hi[2 * p][1] = q[2];
                b_hi[2 * p + 1][0] = q[1]; b_hi[2 * p + 1][1] = q[3];
                ldsm_x4(q, bB[bCur][1] + off);
                b_lo[2 * p][0] = q[0]; b_lo[2 * p][1] = q[2];
                b_lo[2 * p + 1][0] = q[1]; b_lo[2 * p + 1][1] = q[3];
            }
#pragma unroll
            for (int mt = 0; mt < 2; mt++)
#pragma unroll
                for (int nt = 0; nt < 4; nt++)
                    mma16816(acc[mt][nt], a_hi[mt], b_hi[nt][0], b_hi[nt][1]);
#pragma unroll
            for (int mt = 0; mt < 2; mt++)
#pragma unroll
                for (int nt = 0; nt < 4; nt++)
                    mma16816(acc[mt][nt], a_hi[mt], b_lo[nt][0], b_lo[nt][1]);
#pragma unroll
            for (int mt = 0; mt < 2; mt++)
#pragma unroll
                for (int nt = 0; nt < 4; nt++)
                    mma16816(acc[mt][nt], a_lo[mt], b_hi[nt][0], b_hi[nt][1]);
        }
        __syncthreads();
    }
}

// q/k/v convs in one launch; grid (16, 32, 3)
__global__ __launch_bounds__(256, 3) void conv_qkv(
    const float* __restrict__ b0, const float* __restrict__ b1, const float* __restrict__ b2)
{
    extern __shared__ char sm[];
    int z = blockIdx.z;
    const float* bias = (z == 0) ? b0 : (z == 1) ? b1 : b2;

    int colTile = blockIdx.x * 64;
    int rowTile = blockIdx.y * 128;
    int b = rowTile >> 10;
    int lbase = rowTile & 1023;

    float acc[2][4][4];
#pragma unroll
    for (int mt = 0; mt < 2; mt++)
#pragma unroll
        for (int nt = 0; nt < 4; nt++)
#pragma unroll
            for (int r = 0; r < 4; r++) acc[mt][nt][r] = 0.f;

    conv_core(g_xhi3[z], g_xlo3[z], g_whi[z], g_wlo[z], sm, b, lbase, colTile, acc);

    int lane = threadIdx.x & 31;
    int w = threadIdx.x >> 5;
    int wm = (w >> 1) * 32;
    int wn = (w & 1) * 32;

    __nv_bfloat16* yh = (z == 0) ? g_qhi : (z == 1) ? g_khi : g_vhi;
    __nv_bfloat16* yl = (z == 0) ? g_qlo : (z == 1) ? g_klo : g_vlo;
#pragma unroll
    for (int nt = 0; nt < 4; nt++) {
        int n0 = colTile + wn + nt * 8 + (lane & 3) * 2;
        float bb0 = bias[n0], bb1 = bias[n0 + 1];
#pragma unroll
        for (int mt = 0; mt < 2; mt++) {
            int m0 = rowTile + wm + mt * 16 + (lane >> 2);
            float* c = acc[mt][nt];
            __nv_bfloat16 h0, l0, h1, l1;
            split_bf16(c[0] + bb0, h0, l0);
            split_bf16(c[1] + bb1, h1, l1);
            *reinterpret_cast<__nv_bfloat162*>(yh + (size_t)m0 * Dm + n0) = __nv_bfloat162(h0, h1);
            *reinterpret_cast<__nv_bfloat162*>(yl + (size_t)m0 * Dm + n0) = __nv_bfloat162(l0, l1);
            split_bf16(c[2] + bb0, h0, l0);
            split_bf16(c[3] + bb1, h1, l1);
            *reinterpret_cast<__nv_bfloat162*>(yh + (size_t)(m0 + 8) * Dm + n0) = __nv_bfloat162(h0, h1);
            *reinterpret_cast<__nv_bfloat162*>(yl + (size_t)(m0 + 8) * Dm + n0) = __nv_bfloat162(l0, l1);
        }
    }
}

// output conv (fp32 out); grid (16, 32)
__global__ __launch_bounds__(256, 3) void conv_o(const float* __restrict__ bias,
                                                 float* __restrict__ yext)
{
    extern __shared__ char sm[];
    int colTile = blockIdx.x * 64;
    int rowTile = blockIdx.y * 128;
    int b = rowTile >> 10;
    int lbase = rowTile & 1023;

    float acc[2][4][4];
#pragma unroll
    for (int mt = 0; mt < 2; mt++)
#pragma unroll
        for (int nt = 0; nt < 4; nt++)
#pragma unroll
            for (int r = 0; r < 4; r++) acc[mt][nt][r] = 0.f;

    conv_core(g_xhi3[0], g_xlo3[0], g_whi[3], g_wlo[3], sm, b, lbase, colTile, acc);

    int lane = threadIdx.x & 31;
    int w = threadIdx.x >> 5;
    int wm = (w >> 1) * 32;
    int wn = (w & 1) * 32;
#pragma unroll
    for (int nt = 0; nt < 4; nt++) {
        int n0 = colTile + wn + nt * 8 + (lane & 3) * 2;
        float bb0 = bias[n0], bb1 = bias[n0 + 1];
#pragma unroll
        for (int mt = 0; mt < 2; mt++) {
            int m0 = rowTile + wm + mt * 16 + (lane >> 2);
            float* c = acc[mt][nt];
            *reinterpret_cast<float2*>(yext + (size_t)m0 * Dm + n0) =
                make_float2(c[0] + bb0, c[1] + bb1);
            *reinterpret_cast<float2*>(yext + (size_t)(m0 + 8) * Dm + n0) =
                make_float2(c[2] + bb0, c[3] + bb1);
        }
    }
}

// ---------------- fused attention (R12 structure + direct split-bf16 output) ----
#define AT_MAT 8192
#define AT_STAGE 32768
#define ATT_SMEM (2 * AT_STAGE + 4096)
#define MASKV (-3.0e38f)

__device__ __forceinline__ uint32_t asw(int row, int col) {
    uint32_t colb = (uint32_t)((col & 31) << 1);
    return (uint32_t)(((col >> 5) << 12) + row * 64 + (colb ^ (((row >> 1) & 3) << 4)));
}

__global__ __launch_bounds__(128, 3) void attn_fused(
    const float* __restrict__ am, const void* __restrict__ kpm)
{
    extern __shared__ char asmem[];
    uint32_t base = smem_u32(asmem);
    float* maskadd = reinterpret_cast<float*>(asmem + 2 * AT_STAGE);

    int bh = blockIdx.y, b = bh >> 4, h = bh & 15;
    int i0 = blockIdx.x * 64;
    int tid = threadIdx.x, lane = tid & 31, w = tid >> 5;
    int wm = w * 16;
    int lrow = lane & 15, lhalf = (lane >> 4) * 8;
    int g = lane >> 2;
    int t2 = (lane & 3) * 2;
    int mword = g_mask_is_word;
    int amnz = g_am_nonzero;

    // ---- build maskadd (once per CTA) ----
    for (int j = tid; j < Lq; j += 128) {
        bool mk = mword ? (((const int*)kpm)[b * Lq + j] != 0)
                        : (((const unsigned char*)kpm)[b * Lq + j] != 0);
        maskadd[j] = mk ? MASKV : 0.f;
    }

    // ---- stage Q into stage-1 buffer (reused by pipeline later) ----
    uint32_t qh_s = base + AT_STAGE;
    uint32_t ql_s = base + AT_STAGE + AT_MAT;
    for (int v = tid; v < 512; v += 128) {
        int r = v >> 3, c = (v & 7) << 3;
        size_t go = ((size_t)((b << 10) + i0 + r)) * Dm + h * HD + c;
        uint32_t d = asw(r, c);
        cp_async16(qh_s + d, g_qhi + go, 16);
        cp_async16(ql_s + d, g_qlo + go, 16);
    }
    CP_COMMIT();
    CP_WAIT0();
    __syncthreads();
    uint32_t qh[4][4], ql[4][4];
#pragma unroll
    for (int ks = 0; ks < 4; ks++) {
        uint32_t d = asw(wm + lrow, ks * 16 + lhalf);
        ldsm_x4(qh[ks], qh_s + d);
        ldsm_x4(ql[ks], ql_s + d);
    }
    __syncthreads();

    auto stageKV = [&](int j0, int s) {
        uint32_t sb = base + (uint32_t)s * AT_STAGE;
        for (int v = tid; v < 2048; v += 128) {
            int mat = v >> 9;
            int r = (v >> 3) & 63;
            int c = (v & 7) << 3;
            size_t go = ((size_t)((b << 10) + j0 + r)) * Dm + h * HD + c;
            const __nv_bfloat16* src = (mat == 0) ? g_khi : (mat == 1) ? g_klo
                                     : (mat == 2) ? g_vhi : g_vlo;
            cp_async16(sb + (uint32_t)mat * AT_MAT + asw(r, c), src + go, 16);
        }
    };

    float m0 = -1e30f, m1 = -1e30f, l0 = 0.f, l1 = 0.f;
    float o[8][4];
#pragma unroll
    for (int nt = 0; nt < 8; nt++)
#pragma unroll
        for (int r = 0; r < 4; r++) o[nt][r] = 0.f;

    int r0g = i0 + wm + g;
    const float* am0 = am + (size_t)r0g * Lq;
    const float* am1 = am0 + 8 * Lq;

    stageKV(0, 0);
    CP_COMMIT();

    for (int jc = 0; jc < 16; ++jc) {
        int j0 = jc * 64;
        int cur = jc & 1;
        if (jc + 1 < 16) stageKV((jc + 1) * 64, (jc + 1) & 1);
        CP_COMMIT();
        CP_WAIT1();
        __syncthreads();

        uint32_t sKh = base + (uint32_t)cur * AT_STAGE;
        uint32_t sKl = sKh + AT_MAT;
        uint32_t sVh = sKh + 2 * AT_MAT;
        uint32_t sVl = sKh + 3 * AT_MAT;

        // ---- S = Q K^T (3-term split) ----
        float s[8][4];
#pragma unroll
        for (int nt = 0; nt < 8; nt++)
#pragma unroll
            for (int r = 0; r < 4; r++) s[nt][r] = 0.f;
#pragma unroll
        for (int ks = 0; ks < 4; ks++) {
#pragma unroll
            for (int p = 0; p < 4; p++) {
                uint32_t d = asw(p * 16 + lrow, ks * 16 + lhalf);
                uint32_t kh4[4], kl4[4];
                ldsm_x4(kh4, sKh + d);
                ldsm_x4(kl4, sKl + d);
                mma16816(s[2 * p],     qh[ks], kh4[0], kh4[2]);
                mma16816(s[2 * p],     qh[ks], kl4[0], kl4[2]);
                mma16816(s[2 * p],     ql[ks], kh4[0], kh4[2]);
                mma16816(s[2 * p + 1], qh[ks], kh4[1], kh4[3]);
                mma16816(s[2 * p + 1], qh[ks], kl4[1], kl4[3]);
                mma16816(s[2 * p + 1], ql[ks], kh4[1], kh4[3]);
            }
        }

        // ---- scale + attn_mask(+0 fast path) + maskadd, row max ----
        float mx0 = MASKV, mx1 = MASKV;
#pragma unroll
        for (int nt = 0; nt < 8; nt++) {
            int c0 = j0 + nt * 8 + t2;
            float a00 = 0.f, a01 = 0.f, a10 = 0.f, a11 = 0.f;
            if (amnz) {
                float2 f0 = *reinterpret_cast<const float2*>(am0 + c0);
                float2 f1 = *reinterpret_cast<const float2*>(am1 + c0);
                a00 = f0.x; a01 = f0.y; a10 = f1.x; a11 = f1.y;
            }
            float k0a = maskadd[c0], k1a = maskadd[c0 + 1];
            s[nt][0] = s[nt][0] * 0.125f + a00 + k0a;
            s[nt][1] = s[nt][1] * 0.125f + a01 + k1a;
            s[nt][2] = s[nt][2] * 0.125f + a10 + k0a;
            s[nt][3] = s[nt][3] * 0.125f + a11 + k1a;
            mx0 = fmaxf(mx0, fmaxf(s[nt][0], s[nt][1]));
            mx1 = fmaxf(mx1, fmaxf(s[nt][2], s[nt][3]));
        }
        mx0 = fmaxf(mx0, __shfl_xor_sync(0xFFFFFFFFu, mx0, 1));
        mx0 = fmaxf(mx0, __shfl_xor_sync(0xFFFFFFFFu, mx0, 2));
        mx1 = fmaxf(mx1, __shfl_xor_sync(0xFFFFFFFFu, mx1, 1));
        mx1 = fmaxf(mx1, __shfl_xor_sync(0xFFFFFFFFu, mx1, 2));

        float mn0 = fmaxf(m0, mx0), mn1 = fmaxf(m1, mx1);
        float sc0 = exp2f((m0 - mn0) * L2E), sc1 = exp2f((m1 - mn1) * L2E);
        m0 = mn0; m1 = mn1;

#pragma unroll
        for (int nt = 0; nt < 8; nt++) {
            o[nt][0] *= sc0; o[nt][1] *= sc0;
            o[nt][2] *= sc1; o[nt][3] *= sc1;
        }

        // ---- per-q: exp/split -> PV MMAs ----
        float sum0 = 0.f, sum1 = 0.f;
#pragma unroll
        for (int q = 0; q < 4; q++) {
            uint32_t ph[4], pl[4];
#pragma unroll
            for (int hh = 0; hh < 2; hh++) {
                int nt = 2 * q + hh;
                float p0 = exp2f((s[nt][0] - m0) * L2E);
                float p1 = exp2f((s[nt][1] - m0) * L2E);
                float p2 = exp2f((s[nt][2] - m1) * L2E);
                float p3 = exp2f((s[nt][3] - m1) * L2E);
                sum0 += p0 + p1;
                sum1 += p2 + p3;
                __nv_bfloat16 h0, e0, h1, e1, h2, e2, h3, e3;
                split_bf16(p0, h0, e0); split_bf16(p1, h1, e1);
                split_bf16(p2, h2, e2); split_bf16(p3, h3, e3);
                ph[0 + 2 * hh] = pack2(h0, h1);
                ph[1 + 2 * hh] = pack2(h2, h3);
                pl[0 + 2 * hh] = pack2(e0, e1);
                pl[1 + 2 * hh] = pack2(e2, e3);
            }
#pragma unroll
            for (int p = 0; p < 4; p++) {
                uint32_t d = asw(q * 16 + lrow, p * 16 + lhalf);
                uint32_t vh4[4], vl4[4];
                ldsm_x4_t(vh4, sVh + d);
                ldsm_x4_t(vl4, sVl + d);
                mma16816(o[2 * p],     ph, vh4[0], vh4[1]);
                mma16816(o[2 * p],     ph, vl4[0], vl4[1]);
                mma16816(o[2 * p],     pl, vh4[0], vh4[1]);
                mma16816(o[2 * p + 1], ph, vh4[2], vh4[3]);
                mma16816(o[2 * p + 1], ph, vl4[2], vl4[3]);
                mma16816(o[2 * p + 1], pl, vh4[2], vh4[3]);
            }
        }
        sum0 += __shfl_xor_sync(0xFFFFFFFFu, sum0, 1);
        sum0 += __shfl_xor_sync(0xFFFFFFFFu, sum0, 2);
        sum1 += __shfl_xor_sync(0xFFFFFFFFu, sum1, 1);
        sum1 += __shfl_xor_sync(0xFFFFFFFFu, sum1, 2);
        l0 = l0 * sc0 + sum0;
        l1 = l1 * sc1 + sum1;
        __syncthreads();
    }

    // ---- normalize + write split-bf16 ctx directly (feeds conv_o) ----
    float inv0 = 1.f / l0, inv1 = 1.f / l1;
    __nv_bfloat16* ch = g_xhi3[0] + ((size_t)((b << 10) + r0g)) * Dm + h * HD;
    __nv_bfloat16* cl = g_xlo3[0] + ((size_t)((b << 10) + r0g)) * Dm + h * HD;
#pragma unroll
    for (int nt = 0; nt < 8; nt++) {
        int n0 = nt * 8 + t2;
        __nv_bfloat16 h0, e0, h1, e1;
        split_bf16(o[nt][0] * inv0, h0, e0);
        split_bf16(o[nt][1] * inv0, h1, e1);
        *reinterpret_cast<__nv_bfloat162*>(ch + n0) = __nv_bfloat162(h0, h1);
        *reinterpret_cast<__nv_bfloat162*>(cl + n0) = __nv_bfloat162(e0, e1);
        split_bf16(o[nt][2] * inv1, h0, e0);
        split_bf16(o[nt][3] * inv1, h1, e1);
        *reinterpret_cast<__nv_bfloat162*>(ch + 8 * Dm + n0) = __nv_bfloat162(h0, h1);
        *reinterpret_cast<__nv_bfloat162*>(cl + 8 * Dm + n0) = __nv_bfloat162(e0, e1);
    }
}

// ---------------- launch ----------------
extern "C" void kernel_launch(void* const* d_in, const int* in_sizes, int n_in,
                              void* d_out, int out_size) {
    const float* qkv[3] = {nullptr, nullptr, nullptr};
    const float* ws[4]  = {nullptr, nullptr, nullptr, nullptr};
    const float* bs[4]  = {nullptr, nullptr, nullptr, nullptr};
    const void*  kpm = nullptr;
    const float* am  = nullptr;
    int nqkv = 0, nw = 0, nb = 0;
    for (int i = 0; i < n_in; ++i) {
        int sz = in_sizes[i];
        if (sz == Bsz * Lq * Dm)           { if (nqkv < 3) qkv[nqkv++] = (const float*)d_in[i]; }
        else if (sz == 3 * Dm * Dm)        { if (nw < 4)   ws[nw++]    = (const float*)d_in[i]; }
        else if (sz == Dm)                 { if (nb < 4)   bs[nb++]    = (const float*)d_in[i]; }
        else if (sz == Bsz * Lq)           { kpm = d_in[i]; }
        else if (sz == Lq * Lq)            { am  = (const float*)d_in[i]; }
    }
    float* out = (float*)d_out;

    cudaFuncSetAttribute(conv_qkv, cudaFuncAttributeMaxDynamicSharedMemorySize, CONV_SMEM);
    cudaFuncSetAttribute(conv_o,   cudaFuncAttributeMaxDynamicSharedMemorySize, CONV_SMEM);
    cudaFuncSetAttribute(attn_fused, cudaFuncAttributeMaxDynamicSharedMemorySize, ATT_SMEM);

    detect_mask<<<1, 256>>>((const unsigned char*)kpm);
    detect_am<<<Lq * Lq / 4 / 256, 256>>>(am);
    prep_w4<<<dim3(3 * Dm * Dm / 256, 4), 256>>>(ws[0], ws[1], ws[2], ws[3]);

    const int PX_GRID = Bsz * Lq * Dm / 4 / 256;
    prep_x3<<<dim3(PX_GRID, 3), 256>>>(qkv[0], qkv[1], qkv[2]);

    conv_qkv<<<dim3(Dm / 64, Bsz * Lq / 128, 3), 256, CONV_SMEM>>>(bs[0], bs[1], bs[2]);

    attn_fused<<<dim3(Lq / 64, Bsz * NH), 128, ATT_SMEM>>>(am, kpm);

    conv_o<<<dim3(Dm / 64, Bsz * Lq / 128), 256, CONV_SMEM>>>(bs[3], out);
}

// round 16
// speedup vs baseline: 1.0705x; 1.0705x over previous
#include <cuda_runtime.h>
#include <cuda_bf16.h>
#include <math.h>
#include <stdint.h>

#define Bsz 4
#define Lq  1024
#define Dm  1024
#define NH  16
#define HD  64
#define L2E 1.4426950408889634f

// ---------------- scratch (static device globals; no allocation) ----------------
__device__ int   g_mask_is_word;
__device__ int   g_am_nonzero;

__device__ __align__(256) __nv_bfloat16 g_xhi3[3][Bsz * Lq * Dm];
__device__ __align__(256) __nv_bfloat16 g_xlo3[3][Bsz * Lq * Dm];
__device__ __align__(256) __nv_bfloat16 g_whi[4][3 * Dm * Dm];  // [sel][t][o][i]
__device__ __align__(256) __nv_bfloat16 g_wlo[4][3 * Dm * Dm];
__device__ __align__(256) __nv_bfloat16 g_qhi[Bsz * Lq * Dm];
__device__ __align__(256) __nv_bfloat16 g_qlo[Bsz * Lq * Dm];
__device__ __align__(256) __nv_bfloat16 g_khi[Bsz * Lq * Dm];
__device__ __align__(256) __nv_bfloat16 g_klo[Bsz * Lq * Dm];
__device__ __align__(256) __nv_bfloat16 g_vhi[Bsz * Lq * Dm];
__device__ __align__(256) __nv_bfloat16 g_vlo[Bsz * Lq * Dm];

// ================= warp-MMA helpers =================
__device__ __forceinline__ uint32_t smem_u32(const void* p) {
    uint32_t a;
    asm("{ .reg .u64 t; cvta.to.shared.u64 t, %1; cvt.u32.u64 %0, t; }"
        : "=r"(a) : "l"(p));
    return a;
}
__device__ __forceinline__ void ldsm_x4(uint32_t* r, uint32_t addr) {
    asm volatile("ldmatrix.sync.aligned.m8n8.x4.shared.b16 {%0,%1,%2,%3}, [%4];"
                 : "=r"(r[0]), "=r"(r[1]), "=r"(r[2]), "=r"(r[3]) : "r"(addr));
}
__device__ __forceinline__ void ldsm_x4_t(uint32_t* r, uint32_t addr) {
    asm volatile("ldmatrix.sync.aligned.m8n8.x4.trans.shared.b16 {%0,%1,%2,%3}, [%4];"
                 : "=r"(r[0]), "=r"(r[1]), "=r"(r[2]), "=r"(r[3]) : "r"(addr));
}
__device__ __forceinline__ void mma16816(float* c, const uint32_t* a,
                                          const uint32_t b0, const uint32_t b1) {
    asm volatile(
        "mma.sync.aligned.m16n8k16.row.col.f32.bf16.bf16.f32 "
        "{%0,%1,%2,%3}, {%4,%5,%6,%7}, {%8,%9}, {%0,%1,%2,%3};"
        : "+f"(c[0]), "+f"(c[1]), "+f"(c[2]), "+f"(c[3])
        : "r"(a[0]), "r"(a[1]), "r"(a[2]), "r"(a[3]), "r"(b0), "r"(b1));
}
__device__ __forceinline__ void cp_async16(uint32_t dst, const void* src, int src_bytes) {
    asm volatile("cp.async.cg.shared.global [%0], [%1], 16, %2;"
                 :: "r"(dst), "l"(src), "r"(src_bytes) : "memory");
}
#define CP_COMMIT() asm volatile("cp.async.commit_group;" ::: "memory")
#define CP_WAIT1()  asm volatile("cp.async.wait_group 1;" ::: "memory")
#define CP_WAIT0()  asm volatile("cp.async.wait_group 0;" ::: "memory")

__device__ __forceinline__ void split_bf16(float x, __nv_bfloat16& h, __nv_bfloat16& l) {
    h = __float2bfloat16_rn(x);
    l = __float2bfloat16_rn(x - __bfloat162float(h));
}
__device__ __forceinline__ uint32_t pack2(__nv_bfloat16 a, __nv_bfloat16 b) {
    __nv_bfloat162 t(a, b);
    return *reinterpret_cast<uint32_t*>(&t);
}

// ---------------- fused mask-dtype + attn_mask-content detection ----------------
// grid 1024 x 256 threads. Every block scans its slice of am; block 0 also
// classifies the padding-mask dtype from its first 4096 bytes.
__global__ void detect_all(const unsigned char* __restrict__ m,
                           const float* __restrict__ am) {
    int tid = threadIdx.x;
    if (blockIdx.x == 0) {
        __shared__ int red[256];
        if (tid == 0) g_am_nonzero = 0;
        int c = 0;
        for (int i = tid; i < 4096; i += 256) c += (m[i] != 0);
        red[tid] = c;
        __syncthreads();
        for (int s = 128; s > 0; s >>= 1) {
            if (tid < s) red[tid] += red[tid + s];
            __syncthreads();
        }
        if (tid == 0) g_mask_is_word = (red[0] < 1536) ? 1 : 0;
    }
    int i = (blockIdx.x * 256 + tid) * 4;
    float4 v = *reinterpret_cast<const float4*>(am + i);
    if (v.x != 0.f || v.y != 0.f || v.z != 0.f || v.w != 0.f)
        atomicOr(&g_am_nonzero, 1);
}

// ---------------- preps ----------------
__global__ void prep_x3(const float* __restrict__ x0, const float* __restrict__ x1,
                        const float* __restrict__ x2) {
    int z = blockIdx.y;
    const float* src = (z == 0) ? x0 : (z == 1) ? x1 : x2;
    int idx = blockIdx.x * blockDim.x + threadIdx.x;
    float4 v = reinterpret_cast<const float4*>(src)[idx];
    __nv_bfloat16 h0, l0, h1, l1, h2, l2, h3, l3;
    split_bf16(v.x, h0, l0); split_bf16(v.y, h1, l1);
    split_bf16(v.z, h2, l2); split_bf16(v.w, h3, l3);
    reinterpret_cast<__nv_bfloat162*>(g_xhi3[z])[idx * 2 + 0] = __nv_bfloat162(h0, h1);
    reinterpret_cast<__nv_bfloat162*>(g_xhi3[z])[idx * 2 + 1] = __nv_bfloat162(h2, h3);
    reinterpret_cast<__nv_bfloat162*>(g_xlo3[z])[idx * 2 + 0] = __nv_bfloat162(l0, l1);
    reinterpret_cast<__nv_bfloat162*>(g_xlo3[z])[idx * 2 + 1] = __nv_bfloat162(l2, l3);
}

// w[o][i][t] -> whi/wlo[sel][t][o][i]; grid (12288, 4)
__global__ void prep_w4(const float* __restrict__ w0, const float* __restrict__ w1,
                        const float* __restrict__ w2, const float* __restrict__ w3) {
    int sel = blockIdx.y;
    const float* w = (sel == 0) ? w0 : (sel == 1) ? w1 : (sel == 2) ? w2 : w3;
    int j = blockIdx.x * blockDim.x + threadIdx.x;
    int t = j >> 20;
    int rem = j & 0xFFFFF;
    int o = rem >> 10;
    int i = rem & 1023;
    float v = w[((size_t)o * Dm + i) * 3 + t];
    __nv_bfloat16 h, l;
    split_bf16(v, h, l);
    g_whi[sel][j] = h;
    g_wlo[sel][j] = l;
}

// ---------------- conv core (R12 structure: issue-before-wait, wait_group 1) ----
#define A_BYTES (130 * 64)
#define B_BYTES (64 * 64)
#define CONV_SMEM (4 * A_BYTES + 4 * B_BYTES)   // 49664 bytes

__device__ __forceinline__ uint32_t csw(int row, int colb) {
    return (uint32_t)(row * 64 + (colb ^ (((row >> 1) & 3) << 4)));
}

__device__ __forceinline__ void conv_core(
    const __nv_bfloat16* __restrict__ xhi, const __nv_bfloat16* __restrict__ xlo,
    const __nv_bfloat16* __restrict__ whi, const __nv_bfloat16* __restrict__ wlo,
    char* sm, int b, int lbase, int colTile, float acc[4][4][4])
{
    int tid = threadIdx.x;
    int lane = tid & 31;
    int w = tid >> 5;
    int wm = (w >> 1) * 64;
    int wn = (w & 1) * 32;
    int lrow = lane & 15;
    int lhalf = (lane >> 4) * 8;

    uint32_t base = smem_u32(sm);
    uint32_t aB[2][2], bB[2][2];
#pragma unroll
    for (int s = 0; s < 2; s++)
#pragma unroll
        for (int hl = 0; hl < 2; hl++) {
            aB[s][hl] = base + (uint32_t)((s * 2 + hl) * A_BYTES);
            bB[s][hl] = base + (uint32_t)(4 * A_BYTES + (s * 2 + hl) * B_BYTES);
        }

    auto stageA = [&](int k0, int s) {
        for (int v = tid; v < 130 * 4; v += 128) {
            int row = v >> 2;
            int colb = (v & 3) << 4;
            int l = lbase + row - 1;
            int nb = (l >= 0 && l < Lq) ? 16 : 0;
            int lc = l < 0 ? 0 : (l > Lq - 1 ? Lq - 1 : l);
            size_t g = ((size_t)(b << 10) + lc) * Dm + k0 + (colb >> 1);
            uint32_t doff = csw(row, colb);
            cp_async16(aB[s][0] + doff, xhi + g, nb);
            cp_async16(aB[s][1] + doff, xlo + g, nb);
        }
    };
    auto stageB = [&](int k0, int t, int s) {
        const __nv_bfloat16* wh = whi + ((size_t)t << 20);
        const __nv_bfloat16* wl = wlo + ((size_t)t << 20);
        for (int v = tid; v < 256; v += 128) {
            int row = v >> 2;
            int colb = (v & 3) << 4;
            size_t gw = (size_t)(colTile + row) * Dm + k0 + (colb >> 1);
            uint32_t doff = csw(row, colb);
            cp_async16(bB[s][0] + doff, wh + gw, 16);
            cp_async16(bB[s][1] + doff, wl + gw, 16);
        }
    };

    stageA(0, 0);
    stageB(0, 0, 0);
    CP_COMMIT();

    for (int it = 0; it < 96; ++it) {
        int t = it - (it / 3) * 3;
        int aCur = (it / 3) & 1;
        int bCur = it & 1;

        int itn = it + 1;
        if (itn < 96) {
            int kn = itn / 3;
            int tn = itn - kn * 3;
            if (tn == 0) stageA(kn * 32, kn & 1);
            stageB(kn * 32, tn, itn & 1);
        }
        CP_COMMIT();
        CP_WAIT1();
        __syncthreads();

#pragma unroll
        for (int ks = 0; ks < 32; ks += 16) {
            int colb = (ks + lhalf) * 2;
            uint32_t a_hi[4][4], a_lo[4][4];
#pragma unroll
            for (int mt = 0; mt < 4; mt++) {
                uint32_t off = csw(wm + mt * 16 + lrow + t, colb);
                ldsm_x4(a_hi[mt], aB[aCur][0] + off);
                ldsm_x4(a_lo[mt], aB[aCur][1] + off);
            }
            uint32_t b_hi[4][2], b_lo[4][2];
#pragma unroll
            for (int p = 0; p < 2; p++) {
                uint32_t off = csw(wn + p * 16 + lrow, colb);
                uint32_t q[4];
                ldsm_x4(q, bB[bCur][0] + off);
                b_hi[2 * p][0] = q[0]; b_hi[2 * p][1] = q[2];
                b_hi[2 * p + 1][0] = q[1]; b_hi[2 * p + 1][1] = q[3];
                ldsm_x4(q, bB[bCur][1] + off);
                b_lo[2 * p][0] = q[0]; b_lo[2 * p][1] = q[2];
                b_lo[2 * p + 1][0] = q[1]; b_lo[2 * p + 1][1] = q[3];
            }
#pragma unroll
            for (int mt = 0; mt < 4; mt++)
#pragma unroll
                for (int nt = 0; nt < 4; nt++)
                    mma16816(acc[mt][nt], a_hi[mt], b_hi[nt][0], b_hi[nt][1]);
#pragma unroll
            for (int mt = 0; mt < 4; mt++)
#pragma unroll
                for (int nt = 0; nt < 4; nt++)
                    mma16816(acc[mt][nt], a_hi[mt], b_lo[nt][0], b_lo[nt][1]);
#pragma unroll
            for (int mt = 0; mt < 4; mt++)
#pragma unroll
                for (int nt = 0; nt < 4; nt++)
                    mma16816(acc[mt][nt], a_lo[mt], b_hi[nt][0], b_hi[nt][1]);
        }
        __syncthreads();
    }
}

// q/k/v convs in one launch; grid (16, 32, 3)
__global__ __launch_bounds__(128, 4) void conv_qkv(
    const float* __restrict__ b0, const float* __restrict__ b1, const float* __restrict__ b2)
{
    extern __shared__ char sm[];
    int z = blockIdx.z;
    const float* bias = (z == 0) ? b0 : (z == 1) ? b1 : b2;

    int colTile = blockIdx.x * 64;
    int rowTile = blockIdx.y * 128;
    int b = rowTile >> 10;
    int lbase = rowTile & 1023;

    float acc[4][4][4];
#pragma unroll
    for (int mt = 0; mt < 4; mt++)
#pragma unroll
        for (int nt = 0; nt < 4; nt++)
#pragma unroll
            for (int r = 0; r < 4; r++) acc[mt][nt][r] = 0.f;

    conv_core(g_xhi3[z], g_xlo3[z], g_whi[z], g_wlo[z], sm, b, lbase, colTile, acc);

    int lane = threadIdx.x & 31;
    int w = threadIdx.x >> 5;
    int wm = (w >> 1) * 64;
    int wn = (w & 1) * 32;

    __nv_bfloat16* yh = (z == 0) ? g_qhi : (z == 1) ? g_khi : g_vhi;
    __nv_bfloat16* yl = (z == 0) ? g_qlo : (z == 1) ? g_klo : g_vlo;
#pragma unroll
    for (int nt = 0; nt < 4; nt++) {
        int n0 = colTile + wn + nt * 8 + (lane & 3) * 2;
        float bb0 = bias[n0], bb1 = bias[n0 + 1];
#pragma unroll
        for (int mt = 0; mt < 4; mt++) {
            int m0 = rowTile + wm + mt * 16 + (lane >> 2);
            float* c = acc[mt][nt];
            __nv_bfloat16 h0, l0, h1, l1;
            split_bf16(c[0] + bb0, h0, l0);
            split_bf16(c[1] + bb1, h1, l1);
            *reinterpret_cast<__nv_bfloat162*>(yh + (size_t)m0 * Dm + n0) = __nv_bfloat162(h0, h1);
            *reinterpret_cast<__nv_bfloat162*>(yl + (size_t)m0 * Dm + n0) = __nv_bfloat162(l0, l1);
            split_bf16(c[2] + bb0, h0, l0);
            split_bf16(c[3] + bb1, h1, l1);
            *reinterpret_cast<__nv_bfloat162*>(yh + (size_t)(m0 + 8) * Dm + n0) = __nv_bfloat162(h0, h1);
            *reinterpret_cast<__nv_bfloat162*>(yl + (size_t)(m0 + 8) * Dm + n0) = __nv_bfloat162(l0, l1);
        }
    }
}

// output conv (fp32 out); grid (16, 32)
__global__ __launch_bounds__(128, 4) void conv_o(const float* __restrict__ bias,
                                                 float* __restrict__ yext)
{
    extern __shared__ char sm[];
    int colTile = blockIdx.x * 64;
    int rowTile = blockIdx.y * 128;
    int b = rowTile >> 10;
    int lbase = rowTile & 1023;

    float acc[4][4][4];
#pragma unroll
    for (int mt = 0; mt < 4; mt++)
#pragma unroll
        for (int nt = 0; nt < 4; nt++)
#pragma unroll
            for (int r = 0; r < 4; r++) acc[mt][nt][r] = 0.f;

    conv_core(g_xhi3[0], g_xlo3[0], g_whi[3], g_wlo[3], sm, b, lbase, colTile, acc);

    int lane = threadIdx.x & 31;
    int w = threadIdx.x >> 5;
    int wm = (w >> 1) * 64;
    int wn = (w & 1) * 32;
#pragma unroll
    for (int nt = 0; nt < 4; nt++) {
        int n0 = colTile + wn + nt * 8 + (lane & 3) * 2;
        float bb0 = bias[n0], bb1 = bias[n0 + 1];
#pragma unroll
        for (int mt = 0; mt < 4; mt++) {
            int m0 = rowTile + wm + mt * 16 + (lane >> 2);
            float* c = acc[mt][nt];
            *reinterpret_cast<float2*>(yext + (size_t)m0 * Dm + n0) =
                make_float2(c[0] + bb0, c[1] + bb1);
            *reinterpret_cast<float2*>(yext + (size_t)(m0 + 8) * Dm + n0) =
                make_float2(c[2] + bb0, c[3] + bb1);
        }
    }
}

// ---------------- fused attention (R12 structure + direct split-bf16 output) ----
#define AT_MAT 8192
#define AT_STAGE 32768
#define ATT_SMEM (2 * AT_STAGE + 4096)
#define MASKV (-3.0e38f)

__device__ __forceinline__ uint32_t asw(int row, int col) {
    uint32_t colb = (uint32_t)((col & 31) << 1);
    return (uint32_t)(((col >> 5) << 12) + row * 64 + (colb ^ (((row >> 1) & 3) << 4)));
}

__global__ __launch_bounds__(128, 3) void attn_fused(
    const float* __restrict__ am, const void* __restrict__ kpm)
{
    extern __shared__ char asmem[];
    uint32_t base = smem_u32(asmem);
    float* maskadd = reinterpret_cast<float*>(asmem + 2 * AT_STAGE);

    int bh = blockIdx.y, b = bh >> 4, h = bh & 15;
    int i0 = blockIdx.x * 64;
    int tid = threadIdx.x, lane = tid & 31, w = tid >> 5;
    int wm = w * 16;
    int lrow = lane & 15, lhalf = (lane >> 4) * 8;
    int g = lane >> 2;
    int t2 = (lane & 3) * 2;
    int mword = g_mask_is_word;
    int amnz = g_am_nonzero;

    // ---- build maskadd (once per CTA) ----
    for (int j = tid; j < Lq; j += 128) {
        bool mk = mword ? (((const int*)kpm)[b * Lq + j] != 0)
                        : (((const unsigned char*)kpm)[b * Lq + j] != 0);
        maskadd[j] = mk ? MASKV : 0.f;
    }

    // ---- stage Q into stage-1 buffer (reused by pipeline later) ----
    uint32_t qh_s = base + AT_STAGE;
    uint32_t ql_s = base + AT_STAGE + AT_MAT;
    for (int v = tid; v < 512; v += 128) {
        int r = v >> 3, c = (v & 7) << 3;
        size_t go = ((size_t)((b << 10) + i0 + r)) * Dm + h * HD + c;
        uint32_t d = asw(r, c);
        cp_async16(qh_s + d, g_qhi + go, 16);
        cp_async16(ql_s + d, g_qlo + go, 16);
    }
    CP_COMMIT();
    CP_WAIT0();
    __syncthreads();
    uint32_t qh[4][4], ql[4][4];
#pragma unroll
    for (int ks = 0; ks < 4; ks++) {
        uint32_t d = asw(wm + lrow, ks * 16 + lhalf);
        ldsm_x4(qh[ks], qh_s + d);
        ldsm_x4(ql[ks], ql_s + d);
    }
    __syncthreads();

    auto stageKV = [&](int j0, int s) {
        uint32_t sb = base + (uint32_t)s * AT_STAGE;
        for (int v = tid; v < 2048; v += 128) {
            int mat = v >> 9;
            int r = (v >> 3) & 63;
            int c = (v & 7) << 3;
            size_t go = ((size_t)((b << 10) + j0 + r)) * Dm + h * HD + c;
            const __nv_bfloat16* src = (mat == 0) ? g_khi : (mat == 1) ? g_klo
                                     : (mat == 2) ? g_vhi : g_vlo;
            cp_async16(sb + (uint32_t)mat * AT_MAT + asw(r, c), src + go, 16);
        }
    };

    float m0 = -1e30f, m1 = -1e30f, l0 = 0.f, l1 = 0.f;
    float o[8][4];
#pragma unroll
    for (int nt = 0; nt < 8; nt++)
#pragma unroll
        for (int r = 0; r < 4; r++) o[nt][r] = 0.f;

    int r0g = i0 + wm + g;
    const float* am0 = am + (size_t)r0g * Lq;
    const float* am1 = am0 + 8 * Lq;

    stageKV(0, 0);
    CP_COMMIT();

    for (int jc = 0; jc < 16; ++jc) {
        int j0 = jc * 64;
        int cur = jc & 1;
        if (jc + 1 < 16) stageKV((jc + 1) * 64, (jc + 1) & 1);
        CP_COMMIT();
        CP_WAIT1();
        __syncthreads();

        uint32_t sKh = base + (uint32_t)cur * AT_STAGE;
        uint32_t sKl = sKh + AT_MAT;
        uint32_t sVh = sKh + 2 * AT_MAT;
        uint32_t sVl = sKh + 3 * AT_MAT;

        // ---- S = Q K^T (3-term split) ----
        float s[8][4];
#pragma unroll
        for (int nt = 0; nt < 8; nt++)
#pragma unroll
            for (int r = 0; r < 4; r++) s[nt][r] = 0.f;
#pragma unroll
        for (int ks = 0; ks < 4; ks++) {
#pragma unroll
            for (int p = 0; p < 4; p++) {
                uint32_t d = asw(p * 16 + lrow, ks * 16 + lhalf);
                uint32_t kh4[4], kl4[4];
                ldsm_x4(kh4, sKh + d);
                ldsm_x4(kl4, sKl + d);
                mma16816(s[2 * p],     qh[ks], kh4[0], kh4[2]);
                mma16816(s[2 * p],     qh[ks], kl4[0], kl4[2]);
                mma16816(s[2 * p],     ql[ks], kh4[0], kh4[2]);
                mma16816(s[2 * p + 1], qh[ks], kh4[1], kh4[3]);
                mma16816(s[2 * p + 1], qh[ks], kl4[1], kl4[3]);
                mma16816(s[2 * p + 1], ql[ks], kh4[1], kh4[3]);
            }
        }

        // ---- scale + attn_mask(+0 fast path) + maskadd, row max ----
        float mx0 = MASKV, mx1 = MASKV;
#pragma unroll
        for (int nt = 0; nt < 8; nt++) {
            int c0 = j0 + nt * 8 + t2;
            float a00 = 0.f, a01 = 0.f, a10 = 0.f, a11 = 0.f;
            if (amnz) {
                float2 f0 = *reinterpret_cast<const float2*>(am0 + c0);
                float2 f1 = *reinterpret_cast<const float2*>(am1 + c0);
                a00 = f0.x; a01 = f0.y; a10 = f1.x; a11 = f1.y;
            }
            float k0a = maskadd[c0], k1a = maskadd[c0 + 1];
            s[nt][0] = s[nt][0] * 0.125f + a00 + k0a;
            s[nt][1] = s[nt][1] * 0.125f + a01 + k1a;
            s[nt][2] = s[nt][2] * 0.125f + a10 + k0a;
            s[nt][3] = s[nt][3] * 0.125f + a11 + k1a;
            mx0 = fmaxf(mx0, fmaxf(s[nt][0], s[nt][1]));
            mx1 = fmaxf(mx1, fmaxf(s[nt][2], s[nt][3]));
        }
        mx0 = fmaxf(mx0, __shfl_xor_sync(0xFFFFFFFFu, mx0, 1));
        mx0 = fmaxf(mx0, __shfl_xor_sync(0xFFFFFFFFu, mx0, 2));
        mx1 = fmaxf(mx1, __shfl_xor_sync(0xFFFFFFFFu, mx1, 1));
        mx1 = fmaxf(mx1, __shfl_xor_sync(0xFFFFFFFFu, mx1, 2));

        float mn0 = fmaxf(m0, mx0), mn1 = fmaxf(m1, mx1);
        float sc0 = exp2f((m0 - mn0) * L2E), sc1 = exp2f((m1 - mn1) * L2E);
        m0 = mn0; m1 = mn1;

#pragma unroll
        for (int nt = 0; nt < 8; nt++) {
            o[nt][0] *= sc0; o[nt][1] *= sc0;
            o[nt][2] *= sc1; o[nt][3] *= sc1;
        }

        // ---- per-q: exp/split -> PV MMAs ----
        float sum0 = 0.f, sum1 = 0.f;
#pragma unroll
        for (int q = 0; q < 4; q++) {
            uint32_t ph[4], pl[4];
#pragma unroll
            for (int hh = 0; hh < 2; hh++) {
                int nt = 2 * q + hh;
                float p0 = exp2f((s[nt][0] - m0) * L2E);
                float p1 = exp2f((s[nt][1] - m0) * L2E);
                float p2 = exp2f((s[nt][2] - m1) * L2E);
                float p3 = exp2f((s[nt][3] - m1) * L2E);
                sum0 += p0 + p1;
                sum1 += p2 + p3;
                __nv_bfloat16 h0, e0, h1, e1, h2, e2, h3, e3;
                split_bf16(p0, h0, e0); split_bf16(p1, h1, e1);
                split_bf16(p2, h2, e2); split_bf16(p3, h3, e3);
                ph[0 + 2 * hh] = pack2(h0, h1);
                ph[1 + 2 * hh] = pack2(h2, h3);
                pl[0 + 2 * hh] = pack2(e0, e1);
                pl[1 + 2 * hh] = pack2(e2, e3);
            }
#pragma unroll
            for (int p = 0; p < 4; p++) {
                uint32_t d = asw(q * 16 + lrow, p * 16 + lhalf);
                uint32_t vh4[4], vl4[4];
                ldsm_x4_t(vh4, sVh + d);
                ldsm_x4_t(vl4, sVl + d);
                mma16816(o[2 * p],     ph, vh4[0], vh4[1]);
                mma16816(o[2 * p],     ph, vl4[0], vl4[1]);
                mma16816(o[2 * p],     pl, vh4[0], vh4[1]);
                mma16816(o[2 * p + 1], ph, vh4[2], vh4[3]);
                mma16816(o[2 * p + 1], ph, vl4[2], vl4[3]);
                mma16816(o[2 * p + 1], pl, vh4[2], vh4[3]);
            }
        }
        sum0 += __shfl_xor_sync(0xFFFFFFFFu, sum0, 1);
        sum0 += __shfl_xor_sync(0xFFFFFFFFu, sum0, 2);
        sum1 += __shfl_xor_sync(0xFFFFFFFFu, sum1, 1);
        sum1 += __shfl_xor_sync(0xFFFFFFFFu, sum1, 2);
        l0 = l0 * sc0 + sum0;
        l1 = l1 * sc1 + sum1;
        __syncthreads();
    }

    // ---- normalize + write split-bf16 ctx directly (feeds conv_o) ----
    float inv0 = 1.f / l0, inv1 = 1.f / l1;
    __nv_bfloat16* ch = g_xhi3[0] + ((size_t)((b << 10) + r0g)) * Dm + h * HD;
    __nv_bfloat16* cl = g_xlo3[0] + ((size_t)((b << 10) + r0g)) * Dm + h * HD;
#pragma unroll
    for (int nt = 0; nt < 8; nt++) {
        int n0 = nt * 8 + t2;
        __nv_bfloat16 h0, e0, h1, e1;
        split_bf16(o[nt][0] * inv0, h0, e0);
        split_bf16(o[nt][1] * inv0, h1, e1);
        *reinterpret_cast<__nv_bfloat162*>(ch + n0) = __nv_bfloat162(h0, h1);
        *reinterpret_cast<__nv_bfloat162*>(cl + n0) = __nv_bfloat162(e0, e1);
        split_bf16(o[nt][2] * inv1, h0, e0);
        split_bf16(o[nt][3] * inv1, h1, e1);
        *reinterpret_cast<__nv_bfloat162*>(ch + 8 * Dm + n0) = __nv_bfloat162(h0, h1);
        *reinterpret_cast<__nv_bfloat162*>(cl + 8 * Dm + n0) = __nv_bfloat162(e0, e1);
    }
}

// ---------------- launch ----------------
extern "C" void kernel_launch(void* const* d_in, const int* in_sizes, int n_in,
                              void* d_out, int out_size) {
    const float* qkv[3] = {nullptr, nullptr, nullptr};
    const float* ws[4]  = {nullptr, nullptr, nullptr, nullptr};
    const float* bs[4]  = {nullptr, nullptr, nullptr, nullptr};
    const void*  kpm = nullptr;
    const float* am  = nullptr;
    int nqkv = 0, nw = 0, nb = 0;
    for (int i = 0; i < n_in; ++i) {
        int sz = in_sizes[i];
        if (sz == Bsz * Lq * Dm)           { if (nqkv < 3) qkv[nqkv++] = (const float*)d_in[i]; }
        else if (sz == 3 * Dm * Dm)        { if (nw < 4)   ws[nw++]    = (const float*)d_in[i]; }
        else if (sz == Dm)                 { if (nb < 4)   bs[nb++]    = (const float*)d_in[i]; }
        else if (sz == Bsz * Lq)           { kpm = d_in[i]; }
        else if (sz == Lq * Lq)            { am  = (const float*)d_in[i]; }
    }
    float* out = (float*)d_out;

    cudaFuncSetAttribute(conv_qkv, cudaFuncAttributeMaxDynamicSharedMemorySize, CONV_SMEM);
    cudaFuncSetAttribute(conv_o,   cudaFuncAttributeMaxDynamicSharedMemorySize, CONV_SMEM);
    cudaFuncSetAttribute(attn_fused, cudaFuncAttributeMaxDynamicSharedMemorySize, ATT_SMEM);

    detect_all<<<Lq * Lq / 4 / 256, 256>>>((const unsigned char*)kpm, am);
    prep_w4<<<dim3(3 * Dm * Dm / 256, 4), 256>>>(ws[0], ws[1], ws[2], ws[3]);

    const int PX_GRID = Bsz * Lq * Dm / 4 / 256;
    prep_x3<<<dim3(PX_GRID, 3), 256>>>(qkv[0], qkv[1], qkv[2]);

    conv_qkv<<<dim3(Dm / 64, Bsz * Lq / 128, 3), 128, CONV_SMEM>>>(bs[0], bs[1], bs[2]);

    attn_fused<<<dim3(Lq / 64, Bsz * NH), 128, ATT_SMEM>>>(am, kpm);

    conv_o<<<dim3(Dm / 64, Bsz * Lq / 128), 128, CONV_SMEM>>>(bs[3], out);
}

// round 17
// speedup vs baseline: 1.3667x; 1.2767x over previous
#include <cuda_runtime.h>
#include <cuda_bf16.h>
#include <cuda_fp16.h>
#include <math.h>
#include <stdint.h>

#define Bsz 4
#define Lq  1024
#define Dm  1024
#define NH  16
#define HD  64
#define L2E 1.4426950408889634f

// ---------------- scratch (static device globals; no allocation) ----------------
__device__ int   g_mask_is_word;
__device__ int   g_am_nonzero;

// conv operands: fp16 (x as exact hi+lo pair, w rounded to single fp16)
__device__ __align__(256) __half g_xhi3[3][Bsz * Lq * Dm];
__device__ __align__(256) __half g_xlo3[3][Bsz * Lq * Dm];
__device__ __align__(256) __half g_wh[4][3 * Dm * Dm];   // [sel][t][o][i]
// attention operands: bf16 3-term split (proven path, unchanged)
__device__ __align__(256) __nv_bfloat16 g_qhi[Bsz * Lq * Dm];
__device__ __align__(256) __nv_bfloat16 g_qlo[Bsz * Lq * Dm];
__device__ __align__(256) __nv_bfloat16 g_khi[Bsz * Lq * Dm];
__device__ __align__(256) __nv_bfloat16 g_klo[Bsz * Lq * Dm];
__device__ __align__(256) __nv_bfloat16 g_vhi[Bsz * Lq * Dm];
__device__ __align__(256) __nv_bfloat16 g_vlo[Bsz * Lq * Dm];

// ================= warp-MMA helpers =================
__device__ __forceinline__ uint32_t smem_u32(const void* p) {
    uint32_t a;
    asm("{ .reg .u64 t; cvta.to.shared.u64 t, %1; cvt.u32.u64 %0, t; }"
        : "=r"(a) : "l"(p));
    return a;
}
__device__ __forceinline__ void ldsm_x4(uint32_t* r, uint32_t addr) {
    asm volatile("ldmatrix.sync.aligned.m8n8.x4.shared.b16 {%0,%1,%2,%3}, [%4];"
                 : "=r"(r[0]), "=r"(r[1]), "=r"(r[2]), "=r"(r[3]) : "r"(addr));
}
__device__ __forceinline__ void ldsm_x4_t(uint32_t* r, uint32_t addr) {
    asm volatile("ldmatrix.sync.aligned.m8n8.x4.trans.shared.b16 {%0,%1,%2,%3}, [%4];"
                 : "=r"(r[0]), "=r"(r[1]), "=r"(r[2]), "=r"(r[3]) : "r"(addr));
}
// bf16 MMA (attention)
__device__ __forceinline__ void mma16816(float* c, const uint32_t* a,
                                          const uint32_t b0, const uint32_t b1) {
    asm volatile(
        "mma.sync.aligned.m16n8k16.row.col.f32.bf16.bf16.f32 "
        "{%0,%1,%2,%3}, {%4,%5,%6,%7}, {%8,%9}, {%0,%1,%2,%3};"
        : "+f"(c[0]), "+f"(c[1]), "+f"(c[2]), "+f"(c[3])
        : "r"(a[0]), "r"(a[1]), "r"(a[2]), "r"(a[3]), "r"(b0), "r"(b1));
}
// fp16 MMA (conv)
__device__ __forceinline__ void mma16816h(float* c, const uint32_t* a,
                                           const uint32_t b0, const uint32_t b1) {
    asm volatile(
        "mma.sync.aligned.m16n8k16.row.col.f32.f16.f16.f32 "
        "{%0,%1,%2,%3}, {%4,%5,%6,%7}, {%8,%9}, {%0,%1,%2,%3};"
        : "+f"(c[0]), "+f"(c[1]), "+f"(c[2]), "+f"(c[3])
        : "r"(a[0]), "r"(a[1]), "r"(a[2]), "r"(a[3]), "r"(b0), "r"(b1));
}
__device__ __forceinline__ void cp_async16(uint32_t dst, const void* src, int src_bytes) {
    asm volatile("cp.async.cg.shared.global [%0], [%1], 16, %2;"
                 :: "r"(dst), "l"(src), "r"(src_bytes) : "memory");
}
#define CP_COMMIT() asm volatile("cp.async.commit_group;" ::: "memory")
#define CP_WAIT1()  asm volatile("cp.async.wait_group 1;" ::: "memory")
#define CP_WAIT0()  asm volatile("cp.async.wait_group 0;" ::: "memory")

__device__ __forceinline__ void split_bf16(float x, __nv_bfloat16& h, __nv_bfloat16& l) {
    h = __float2bfloat16_rn(x);
    l = __float2bfloat16_rn(x - __bfloat162float(h));
}
__device__ __forceinline__ void split_f16(float x, __half& h, __half& l) {
    h = __float2half_rn(x);
    l = __float2half_rn(x - __half2float(h));
}
__device__ __forceinline__ uint32_t pack2(__nv_bfloat16 a, __nv_bfloat16 b) {
    __nv_bfloat162 t(a, b);
    return *reinterpret_cast<uint32_t*>(&t);
}

// ---------------- fused mask-dtype + attn_mask-content detection ----------------
__global__ void detect_all(const unsigned char* __restrict__ m,
                           const float* __restrict__ am) {
    int tid = threadIdx.x;
    if (blockIdx.x == 0) {
        __shared__ int red[256];
        if (tid == 0) g_am_nonzero = 0;
        int c = 0;
        for (int i = tid; i < 4096; i += 256) c += (m[i] != 0);
        red[tid] = c;
        __syncthreads();
        for (int s = 128; s > 0; s >>= 1) {
            if (tid < s) red[tid] += red[tid + s];
            __syncthreads();
        }
        if (tid == 0) g_mask_is_word = (red[0] < 1536) ? 1 : 0;
    }
    int i = (blockIdx.x * 256 + tid) * 4;
    float4 v = *reinterpret_cast<const float4*>(am + i);
    if (v.x != 0.f || v.y != 0.f || v.z != 0.f || v.w != 0.f)
        atomicOr(&g_am_nonzero, 1);
}

// ---------------- preps ----------------
__global__ void prep_x3(const float* __restrict__ x0, const float* __restrict__ x1,
                        const float* __restrict__ x2) {
    int z = blockIdx.y;
    const float* src = (z == 0) ? x0 : (z == 1) ? x1 : x2;
    int idx = blockIdx.x * blockDim.x + threadIdx.x;
    float4 v = reinterpret_cast<const float4*>(src)[idx];
    __half h0, l0, h1, l1, h2, l2, h3, l3;
    split_f16(v.x, h0, l0); split_f16(v.y, h1, l1);
    split_f16(v.z, h2, l2); split_f16(v.w, h3, l3);
    reinterpret_cast<__half2*>(g_xhi3[z])[idx * 2 + 0] = __halves2half2(h0, h1);
    reinterpret_cast<__half2*>(g_xhi3[z])[idx * 2 + 1] = __halves2half2(h2, h3);
    reinterpret_cast<__half2*>(g_xlo3[z])[idx * 2 + 0] = __halves2half2(l0, l1);
    reinterpret_cast<__half2*>(g_xlo3[z])[idx * 2 + 1] = __halves2half2(l2, l3);
}

// w[o][i][t] -> wh[sel][t][o][i] (single fp16); grid (12288, 4)
__global__ void prep_w4(const float* __restrict__ w0, const float* __restrict__ w1,
                        const float* __restrict__ w2, const float* __restrict__ w3) {
    int sel = blockIdx.y;
    const float* w = (sel == 0) ? w0 : (sel == 1) ? w1 : (sel == 2) ? w2 : w3;
    int j = blockIdx.x * blockDim.x + threadIdx.x;
    int t = j >> 20;
    int rem = j & 0xFFFFF;
    int o = rem >> 10;
    int i = rem & 1023;
    float v = w[((size_t)o * Dm + i) * 3 + t];
    g_wh[sel][j] = __float2half_rn(v);
}

// ---------------- conv core (fp16 2-term: acc += xh*wh + xl*wh) -----------------
#define A_BYTES (130 * 64)
#define B_BYTES (64 * 64)
#define CONV_SMEM (4 * A_BYTES + 2 * B_BYTES)   // 41472 bytes

__device__ __forceinline__ uint32_t csw(int row, int colb) {
    return (uint32_t)(row * 64 + (colb ^ (((row >> 1) & 3) << 4)));
}

__device__ __forceinline__ void conv_core(
    const __half* __restrict__ xhi, const __half* __restrict__ xlo,
    const __half* __restrict__ wh,
    char* sm, int b, int lbase, int colTile, float acc[4][4][4])
{
    int tid = threadIdx.x;
    int lane = tid & 31;
    int w = tid >> 5;
    int wm = (w >> 1) * 64;
    int wn = (w & 1) * 32;
    int lrow = lane & 15;
    int lhalf = (lane >> 4) * 8;

    uint32_t base = smem_u32(sm);
    uint32_t aB[2][2], bB[2];
#pragma unroll
    for (int s = 0; s < 2; s++) {
#pragma unroll
        for (int hl = 0; hl < 2; hl++)
            aB[s][hl] = base + (uint32_t)((s * 2 + hl) * A_BYTES);
        bB[s] = base + (uint32_t)(4 * A_BYTES + s * B_BYTES);
    }

    auto stageA = [&](int k0, int s) {
        for (int v = tid; v < 130 * 4; v += 128) {
            int row = v >> 2;
            int colb = (v & 3) << 4;
            int l = lbase + row - 1;
            int nb = (l >= 0 && l < Lq) ? 16 : 0;
            int lc = l < 0 ? 0 : (l > Lq - 1 ? Lq - 1 : l);
            size_t g = ((size_t)(b << 10) + lc) * Dm + k0 + (colb >> 1);
            uint32_t doff = csw(row, colb);
            cp_async16(aB[s][0] + doff, xhi + g, nb);
            cp_async16(aB[s][1] + doff, xlo + g, nb);
        }
    };
    auto stageB = [&](int k0, int t, int s) {
        const __half* wt = wh + ((size_t)t << 20);
        for (int v = tid; v < 256; v += 128) {
            int row = v >> 2;
            int colb = (v & 3) << 4;
            size_t gw = (size_t)(colTile + row) * Dm + k0 + (colb >> 1);
            cp_async16(bB[s] + csw(row, colb), wt + gw, 16);
        }
    };

    stageA(0, 0);
    stageB(0, 0, 0);
    CP_COMMIT();

    for (int it = 0; it < 96; ++it) {
        int t = it - (it / 3) * 3;
        int aCur = (it / 3) & 1;
        int bCur = it & 1;

        int itn = it + 1;
        if (itn < 96) {
            int kn = itn / 3;
            int tn = itn - kn * 3;
            if (tn == 0) stageA(kn * 32, kn & 1);
            stageB(kn * 32, tn, itn & 1);
        }
        CP_COMMIT();
        CP_WAIT1();
        __syncthreads();

#pragma unroll
        for (int ks = 0; ks < 32; ks += 16) {
            int colb = (ks + lhalf) * 2;
            uint32_t a_hi[4][4], a_lo[4][4];
#pragma unroll
            for (int mt = 0; mt < 4; mt++) {
                uint32_t off = csw(wm + mt * 16 + lrow + t, colb);
                ldsm_x4(a_hi[mt], aB[aCur][0] + off);
                ldsm_x4(a_lo[mt], aB[aCur][1] + off);
            }
            uint32_t b_h[4][2];
#pragma unroll
            for (int p = 0; p < 2; p++) {
                uint32_t off = csw(wn + p * 16 + lrow, colb);
                uint32_t q[4];
                ldsm_x4(q, bB[bCur] + off);
                b_h[2 * p][0] = q[0]; b_h[2 * p][1] = q[2];
                b_h[2 * p + 1][0] = q[1]; b_h[2 * p + 1][1] = q[3];
            }
#pragma unroll
            for (int mt = 0; mt < 4; mt++)
#pragma unroll
                for (int nt = 0; nt < 4; nt++)
                    mma16816h(acc[mt][nt], a_hi[mt], b_h[nt][0], b_h[nt][1]);
#pragma unroll
            for (int mt = 0; mt < 4; mt++)
#pragma unroll
                for (int nt = 0; nt < 4; nt++)
                    mma16816h(acc[mt][nt], a_lo[mt], b_h[nt][0], b_h[nt][1]);
        }
        __syncthreads();
    }
}

// q/k/v convs in one launch; grid (16, 32, 3)
__global__ __launch_bounds__(128, 4) void conv_qkv(
    const float* __restrict__ b0, const float* __restrict__ b1, const float* __restrict__ b2)
{
    extern __shared__ char sm[];
    int z = blockIdx.z;
    const float* bias = (z == 0) ? b0 : (z == 1) ? b1 : b2;

    int colTile = blockIdx.x * 64;
    int rowTile = blockIdx.y * 128;
    int b = rowTile >> 10;
    int lbase = rowTile & 1023;

    float acc[4][4][4];
#pragma unroll
    for (int mt = 0; mt < 4; mt++)
#pragma unroll
        for (int nt = 0; nt < 4; nt++)
#pragma unroll
            for (int r = 0; r < 4; r++) acc[mt][nt][r] = 0.f;

    conv_core(g_xhi3[z], g_xlo3[z], g_wh[z], sm, b, lbase, colTile, acc);

    int lane = threadIdx.x & 31;
    int w = threadIdx.x >> 5;
    int wm = (w >> 1) * 64;
    int wn = (w & 1) * 32;

    __nv_bfloat16* yh = (z == 0) ? g_qhi : (z == 1) ? g_khi : g_vhi;
    __nv_bfloat16* yl = (z == 0) ? g_qlo : (z == 1) ? g_klo : g_vlo;
#pragma unroll
    for (int nt = 0; nt < 4; nt++) {
        int n0 = colTile + wn + nt * 8 + (lane & 3) * 2;
        float bb0 = bias[n0], bb1 = bias[n0 + 1];
#pragma unroll
        for (int mt = 0; mt < 4; mt++) {
            int m0 = rowTile + wm + mt * 16 + (lane >> 2);
            float* c = acc[mt][nt];
            __nv_bfloat16 h0, l0, h1, l1;
            split_bf16(c[0] + bb0, h0, l0);
            split_bf16(c[1] + bb1, h1, l1);
            *reinterpret_cast<__nv_bfloat162*>(yh + (size_t)m0 * Dm + n0) = __nv_bfloat162(h0, h1);
            *reinterpret_cast<__nv_bfloat162*>(yl + (size_t)m0 * Dm + n0) = __nv_bfloat162(l0, l1);
            split_bf16(c[2] + bb0, h0, l0);
            split_bf16(c[3] + bb1, h1, l1);
            *reinterpret_cast<__nv_bfloat162*>(yh + (size_t)(m0 + 8) * Dm + n0) = __nv_bfloat162(h0, h1);
            *reinterpret_cast<__nv_bfloat162*>(yl + (size_t)(m0 + 8) * Dm + n0) = __nv_bfloat162(l0, l1);
        }
    }
}

// output conv (fp32 out); grid (16, 32)
__global__ __launch_bounds__(128, 4) void conv_o(const float* __restrict__ bias,
                                                 float* __restrict__ yext)
{
    extern __shared__ char sm[];
    int colTile = blockIdx.x * 64;
    int rowTile = blockIdx.y * 128;
    int b = rowTile >> 10;
    int lbase = rowTile & 1023;

    float acc[4][4][4];
#pragma unroll
    for (int mt = 0; mt < 4; mt++)
#pragma unroll
        for (int nt = 0; nt < 4; nt++)
#pragma unroll
            for (int r = 0; r < 4; r++) acc[mt][nt][r] = 0.f;

    conv_core(g_xhi3[0], g_xlo3[0], g_wh[3], sm, b, lbase, colTile, acc);

    int lane = threadIdx.x & 31;
    int w = threadIdx.x >> 5;
    int wm = (w >> 1) * 64;
    int wn = (w & 1) * 32;
#pragma unroll
    for (int nt = 0; nt < 4; nt++) {
        int n0 = colTile + wn + nt * 8 + (lane & 3) * 2;
        float bb0 = bias[n0], bb1 = bias[n0 + 1];
#pragma unroll
        for (int mt = 0; mt < 4; mt++) {
            int m0 = rowTile + wm + mt * 16 + (lane >> 2);
            float* c = acc[mt][nt];
            *reinterpret_cast<float2*>(yext + (size_t)m0 * Dm + n0) =
                make_float2(c[0] + bb0, c[1] + bb1);
            *reinterpret_cast<float2*>(yext + (size_t)(m0 + 8) * Dm + n0) =
                make_float2(c[2] + bb0, c[3] + bb1);
        }
    }
}

// ---------------- fused attention (unchanged bf16 3-term; fp16 ctx output) ------
#define AT_MAT 8192
#define AT_STAGE 32768
#define ATT_SMEM (2 * AT_STAGE + 4096)
#define MASKV (-3.0e38f)

__device__ __forceinline__ uint32_t asw(int row, int col) {
    uint32_t colb = (uint32_t)((col & 31) << 1);
    return (uint32_t)(((col >> 5) << 12) + row * 64 + (colb ^ (((row >> 1) & 3) << 4)));
}

__global__ __launch_bounds__(128, 3) void attn_fused(
    const float* __restrict__ am, const void* __restrict__ kpm)
{
    extern __shared__ char asmem[];
    uint32_t base = smem_u32(asmem);
    float* maskadd = reinterpret_cast<float*>(asmem + 2 * AT_STAGE);

    int bh = blockIdx.y, b = bh >> 4, h = bh & 15;
    int i0 = blockIdx.x * 64;
    int tid = threadIdx.x, lane = tid & 31, w = tid >> 5;
    int wm = w * 16;
    int lrow = lane & 15, lhalf = (lane >> 4) * 8;
    int g = lane >> 2;
    int t2 = (lane & 3) * 2;
    int mword = g_mask_is_word;
    int amnz = g_am_nonzero;

    for (int j = tid; j < Lq; j += 128) {
        bool mk = mword ? (((const int*)kpm)[b * Lq + j] != 0)
                        : (((const unsigned char*)kpm)[b * Lq + j] != 0);
        maskadd[j] = mk ? MASKV : 0.f;
    }

    uint32_t qh_s = base + AT_STAGE;
    uint32_t ql_s = base + AT_STAGE + AT_MAT;
    for (int v = tid; v < 512; v += 128) {
        int r = v >> 3, c = (v & 7) << 3;
        size_t go = ((size_t)((b << 10) + i0 + r)) * Dm + h * HD + c;
        uint32_t d = asw(r, c);
        cp_async16(qh_s + d, g_qhi + go, 16);
        cp_async16(ql_s + d, g_qlo + go, 16);
    }
    CP_COMMIT();
    CP_WAIT0();
    __syncthreads();
    uint32_t qh[4][4], ql[4][4];
#pragma unroll
    for (int ks = 0; ks < 4; ks++) {
        uint32_t d = asw(wm + lrow, ks * 16 + lhalf);
        ldsm_x4(qh[ks], qh_s + d);
        ldsm_x4(ql[ks], ql_s + d);
    }
    __syncthreads();

    auto stageKV = [&](int j0, int s) {
        uint32_t sb = base + (uint32_t)s * AT_STAGE;
        for (int v = tid; v < 2048; v += 128) {
            int mat = v >> 9;
            int r = (v >> 3) & 63;
            int c = (v & 7) << 3;
            size_t go = ((size_t)((b << 10) + j0 + r)) * Dm + h * HD + c;
            const __nv_bfloat16* src = (mat == 0) ? g_khi : (mat == 1) ? g_klo
                                     : (mat == 2) ? g_vhi : g_vlo;
            cp_async16(sb + (uint32_t)mat * AT_MAT + asw(r, c), src + go, 16);
        }
    };

    float m0 = -1e30f, m1 = -1e30f, l0 = 0.f, l1 = 0.f;
    float o[8][4];
#pragma unroll
    for (int nt = 0; nt < 8; nt++)
#pragma unroll
        for (int r = 0; r < 4; r++) o[nt][r] = 0.f;

    int r0g = i0 + wm + g;
    const float* am0 = am + (size_t)r0g * Lq;
    const float* am1 = am0 + 8 * Lq;

    stageKV(0, 0);
    CP_COMMIT();

    for (int jc = 0; jc < 16; ++jc) {
        int j0 = jc * 64;
        int cur = jc & 1;
        if (jc + 1 < 16) stageKV((jc + 1) * 64, (jc + 1) & 1);
        CP_COMMIT();
        CP_WAIT1();
        __syncthreads();

        uint32_t sKh = base + (uint32_t)cur * AT_STAGE;
        uint32_t sKl = sKh + AT_MAT;
        uint32_t sVh = sKh + 2 * AT_MAT;
        uint32_t sVl = sKh + 3 * AT_MAT;

        float s[8][4];
#pragma unroll
        for (int nt = 0; nt < 8; nt++)
#pragma unroll
            for (int r = 0; r < 4; r++) s[nt][r] = 0.f;
#pragma unroll
        for (int ks = 0; ks < 4; ks++) {
#pragma unroll
            for (int p = 0; p < 4; p++) {
                uint32_t d = asw(p * 16 + lrow, ks * 16 + lhalf);
                uint32_t kh4[4], kl4[4];
                ldsm_x4(kh4, sKh + d);
                ldsm_x4(kl4, sKl + d);
                mma16816(s[2 * p],     qh[ks], kh4[0], kh4[2]);
                mma16816(s[2 * p],     qh[ks], kl4[0], kl4[2]);
                mma16816(s[2 * p],     ql[ks], kh4[0], kh4[2]);
                mma16816(s[2 * p + 1], qh[ks], kh4[1], kh4[3]);
                mma16816(s[2 * p + 1], qh[ks], kl4[1], kl4[3]);
                mma16816(s[2 * p + 1], ql[ks], kh4[1], kh4[3]);
            }
        }

        float mx0 = MASKV, mx1 = MASKV;
#pragma unroll
        for (int nt = 0; nt < 8; nt++) {
            int c0 = j0 + nt * 8 + t2;
            float a00 = 0.f, a01 = 0.f, a10 = 0.f, a11 = 0.f;
            if (amnz) {
                float2 f0 = *reinterpret_cast<const float2*>(am0 + c0);
                float2 f1 = *reinterpret_cast<const float2*>(am1 + c0);
                a00 = f0.x; a01 = f0.y; a10 = f1.x; a11 = f1.y;
            }
            float k0a = maskadd[c0], k1a = maskadd[c0 + 1];
            s[nt][0] = s[nt][0] * 0.125f + a00 + k0a;
            s[nt][1] = s[nt][1] * 0.125f + a01 + k1a;
            s[nt][2] = s[nt][2] * 0.125f + a10 + k0a;
            s[nt][3] = s[nt][3] * 0.125f + a11 + k1a;
            mx0 = fmaxf(mx0, fmaxf(s[nt][0], s[nt][1]));
            mx1 = fmaxf(mx1, fmaxf(s[nt][2], s[nt][3]));
        }
        mx0 = fmaxf(mx0, __shfl_xor_sync(0xFFFFFFFFu, mx0, 1));
        mx0 = fmaxf(mx0, __shfl_xor_sync(0xFFFFFFFFu, mx0, 2));
        mx1 = fmaxf(mx1, __shfl_xor_sync(0xFFFFFFFFu, mx1, 1));
        mx1 = fmaxf(mx1, __shfl_xor_sync(0xFFFFFFFFu, mx1, 2));

        float mn0 = fmaxf(m0, mx0), mn1 = fmaxf(m1, mx1);
        float sc0 = exp2f((m0 - mn0) * L2E), sc1 = exp2f((m1 - mn1) * L2E);
        m0 = mn0; m1 = mn1;

#pragma unroll
        for (int nt = 0; nt < 8; nt++) {
            o[nt][0] *= sc0; o[nt][1] *= sc0;
            o[nt][2] *= sc1; o[nt][3] *= sc1;
        }

        float sum0 = 0.f, sum1 = 0.f;
#pragma unroll
        for (int q = 0; q < 4; q++) {
            uint32_t ph[4], pl[4];
#pragma unroll
            for (int hh = 0; hh < 2; hh++) {
                int nt = 2 * q + hh;
                float p0 = exp2f((s[nt][0] - m0) * L2E);
                float p1 = exp2f((s[nt][1] - m0) * L2E);
                float p2 = exp2f((s[nt][2] - m1) * L2E);
                float p3 = exp2f((s[nt][3] - m1) * L2E);
                sum0 += p0 + p1;
                sum1 += p2 + p3;
                __nv_bfloat16 h0, e0, h1, e1, h2, e2, h3, e3;
                split_bf16(p0, h0, e0); split_bf16(p1, h1, e1);
                split_bf16(p2, h2, e2); split_bf16(p3, h3, e3);
                ph[0 + 2 * hh] = pack2(h0, h1);
                ph[1 + 2 * hh] = pack2(h2, h3);
                pl[0 + 2 * hh] = pack2(e0, e1);
                pl[1 + 2 * hh] = pack2(e2, e3);
            }
#pragma unroll
            for (int p = 0; p < 4; p++) {
                uint32_t d = asw(q * 16 + lrow, p * 16 + lhalf);
                uint32_t vh4[4], vl4[4];
                ldsm_x4_t(vh4, sVh + d);
                ldsm_x4_t(vl4, sVl + d);
                mma16816(o[2 * p],     ph, vh4[0], vh4[1]);
                mma16816(o[2 * p],     ph, vl4[0], vl4[1]);
                mma16816(o[2 * p],     pl, vh4[0], vh4[1]);
                mma16816(o[2 * p + 1], ph, vh4[2], vh4[3]);
                mma16816(o[2 * p + 1], ph, vl4[2], vl4[3]);
                mma16816(o[2 * p + 1], pl, vh4[2], vh4[3]);
            }
        }
        sum0 += __shfl_xor_sync(0xFFFFFFFFu, sum0, 1);
        sum0 += __shfl_xor_sync(0xFFFFFFFFu, sum0, 2);
        sum1 += __shfl_xor_sync(0xFFFFFFFFu, sum1, 1);
        sum1 += __shfl_xor_sync(0xFFFFFFFFu, sum1, 2);
        l0 = l0 * sc0 + sum0;
        l1 = l1 * sc1 + sum1;
        __syncthreads();
    }

    // ---- normalize + write fp16-split ctx directly (feeds fp16 conv_o) ----
    float inv0 = 1.f / l0, inv1 = 1.f / l1;
    __half* ch = g_xhi3[0] + ((size_t)((b << 10) + r0g)) * Dm + h * HD;
    __half* cl = g_xlo3[0] + ((size_t)((b << 10) + r0g)) * Dm + h * HD;
#pragma unroll
    for (int nt = 0; nt < 8; nt++) {
        int n0 = nt * 8 + t2;
        __half h0, e0, h1, e1;
        split_f16(o[nt][0] * inv0, h0, e0);
        split_f16(o[nt][1] * inv0, h1, e1);
        *reinterpret_cast<__half2*>(ch + n0) = __halves2half2(h0, h1);
        *reinterpret_cast<__half2*>(cl + n0) = __halves2half2(e0, e1);
        split_f16(o[nt][2] * inv1, h0, e0);
        split_f16(o[nt][3] * inv1, h1, e1);
        *reinterpret_cast<__half2*>(ch + 8 * Dm + n0) = __halves2half2(h0, h1);
        *reinterpret_cast<__half2*>(cl + 8 * Dm + n0) = __halves2half2(e0, e1);
    }
}

// ---------------- launch ----------------
extern "C" void kernel_launch(void* const* d_in, const int* in_sizes, int n_in,
                              void* d_out, int out_size) {
    const float* qkv[3] = {nullptr, nullptr, nullptr};
    const float* ws[4]  = {nullptr, nullptr, nullptr, nullptr};
    const float* bs[4]  = {nullptr, nullptr, nullptr, nullptr};
    const void*  kpm = nullptr;
    const float* am  = nullptr;
    int nqkv = 0, nw = 0, nb = 0;
    for (int i = 0; i < n_in; ++i) {
        int sz = in_sizes[i];
        if (sz == Bsz * Lq * Dm)           { if (nqkv < 3) qkv[nqkv++] = (const float*)d_in[i]; }
        else if (sz == 3 * Dm * Dm)        { if (nw < 4)   ws[nw++]    = (const float*)d_in[i]; }
        else if (sz == Dm)                 { if (nb < 4)   bs[nb++]    = (const float*)d_in[i]; }
        else if (sz == Bsz * Lq)           { kpm = d_in[i]; }
        else if (sz == Lq * Lq)            { am  = (const float*)d_in[i]; }
    }
    float* out = (float*)d_out;

    cudaFuncSetAttribute(conv_qkv, cudaFuncAttributeMaxDynamicSharedMemorySize, CONV_SMEM);
    cudaFuncSetAttribute(conv_o,   cudaFuncAttributeMaxDynamicSharedMemorySize, CONV_SMEM);
    cudaFuncSetAttribute(attn_fused, cudaFuncAttributeMaxDynamicSharedMemorySize, ATT_SMEM);

    detect_all<<<Lq * Lq / 4 / 256, 256>>>((const unsigned char*)kpm, am);
    prep_w4<<<dim3(3 * Dm * Dm / 256, 4), 256>>>(ws[0], ws[1], ws[2], ws[3]);

    const int PX_GRID = Bsz * Lq * Dm / 4 / 256;
    prep_x3<<<dim3(PX_GRID, 3), 256>>>(qkv[0], qkv[1], qkv[2]);

    conv_qkv<<<dim3(Dm / 64, Bsz * Lq / 128, 3), 128, CONV_SMEM>>>(bs[0], bs[1], bs[2]);

    attn_fused<<<dim3(Lq / 64, Bsz * NH), 128, ATT_SMEM>>>(am, kpm);

    conv_o<<<dim3(Dm / 64, Bsz * Lq / 128), 128, CONV_SMEM>>>(bs[3], out);
}